// round 3
// baseline (speedup 1.0000x reference)
#include <cuda_runtime.h>

#define BH 64
#define SEQ 8192
#define D 64
#define SPLITS 8
#define RPS (SEQ / SPLITS)       // 1024 rows per split
#define CHUNK 16
#define NCH (RPS / CHUNK)        // 64 chunks
#define PART_STRIDE (D * D + D)  // numer[4096] + z[64]

__device__ float g_part[BH * SPLITS * PART_STRIDE];  // ~8.5 MB scratch
__device__ float g_ctx[BH * D * D];

typedef unsigned long long ull;

__device__ __forceinline__ void fma2(ull& acc, ull a, ull b) {
    asm("fma.rn.f32x2 %0, %1, %2, %0;" : "+l"(acc) : "l"(a), "l"(b));
}
__device__ __forceinline__ void unpack2(ull v, float& x, float& y) {
    asm("mov.b64 {%0, %1}, %2;" : "=f"(x), "=f"(y) : "l"(v));
}

// ================= Kernel 1: partial context  exp(K)^T @ V  =================
// grid (BH, SPLITS), 256 threads. Double-buffered smem, pre-packed pairs.
// ek2[r][2*pi(d)+{0,1}] = exp(k[r,d]) duplicated; pi(d)=((d&3)<<4)|(d>>2)
// (permutation makes the duplicated STS.64 conflict-free).
__global__ void __launch_bounds__(256) ctx_partial_kernel(
    const float* __restrict__ k, const float* __restrict__ v) {
    const int head = blockIdx.x, split = blockIdx.y;
    const float* kb = k + (size_t)head * SEQ * D + (size_t)split * RPS * D;
    const float* vb = v + (size_t)head * SEQ * D + (size_t)split * RPS * D;

    __shared__ __align__(16) float ek2[2][CHUNK][2 * D];   // 16 KB
    __shared__ __align__(16) float vv[2][CHUNK][D + 4];    // 8.5 KB (pad 68)

    const int tid = threadIdx.x;
    const int tx = tid & 15;        // e-group (compute)
    const int ty = tid >> 4;        // d-group (compute)
    const int kr = tid >> 4;        // staging row 0..15
    const int c16 = tid & 15;       // staging col group
    const int kc4 = c16 << 2;

    ull acc[4][2];
#pragma unroll
    for (int i = 0; i < 4; i++) { acc[i][0] = 0ULL; acc[i][1] = 0ULL; }
    float zacc = 0.0f;

    float4 kreg = *(const float4*)&kb[kr * D + kc4];
    float4 vreg = *(const float4*)&vb[kr * D + kc4];

    // store chunk 0 -> buf 0
    {
        float2 pp;
        pp.x = pp.y = __expf(kreg.x); *(float2*)&ek2[0][kr][2 * (0 * 16 + c16)] = pp;
        pp.x = pp.y = __expf(kreg.y); *(float2*)&ek2[0][kr][2 * (1 * 16 + c16)] = pp;
        pp.x = pp.y = __expf(kreg.z); *(float2*)&ek2[0][kr][2 * (2 * 16 + c16)] = pp;
        pp.x = pp.y = __expf(kreg.w); *(float2*)&ek2[0][kr][2 * (3 * 16 + c16)] = pp;
        *(float4*)&vv[0][kr][kc4] = vreg;
    }
    __syncthreads();

    for (int c = 0; c < NCH; c++) {
        const int p = c & 1;
        if (c + 1 < NCH) {
            kreg = *(const float4*)&kb[(c + 1) * CHUNK * D + kr * D + kc4];
            vreg = *(const float4*)&vb[(c + 1) * CHUNK * D + kr * D + kc4];
        }
#pragma unroll
        for (int r = 0; r < CHUNK; r++) {
            ulonglong2 B = *(const ulonglong2*)&vv[p][r][tx << 2];
#pragma unroll
            for (int i = 0; i < 4; i++) {
                // d = ty*4+i  ->  pi(d) = (i<<4)|ty
                ull a = *(const ull*)&ek2[p][r][2 * ((i << 4) | ty)];
                fma2(acc[i][0], a, B.x);
                fma2(acc[i][1], a, B.y);
            }
        }
        if (tid < D) {
            const int g2 = 2 * (((tid & 3) << 4) | (tid >> 2));
#pragma unroll
            for (int r = 0; r < CHUNK; r++) zacc += ek2[p][r][g2];
        }
        if (c + 1 < NCH) {
            const int b = p ^ 1;
            float2 pp;
            pp.x = pp.y = __expf(kreg.x); *(float2*)&ek2[b][kr][2 * (0 * 16 + c16)] = pp;
            pp.x = pp.y = __expf(kreg.y); *(float2*)&ek2[b][kr][2 * (1 * 16 + c16)] = pp;
            pp.x = pp.y = __expf(kreg.z); *(float2*)&ek2[b][kr][2 * (2 * 16 + c16)] = pp;
            pp.x = pp.y = __expf(kreg.w); *(float2*)&ek2[b][kr][2 * (3 * 16 + c16)] = pp;
            *(float4*)&vv[b][kr][kc4] = vreg;
        }
        __syncthreads();
    }

    float* np = g_part + (size_t)(head * SPLITS + split) * PART_STRIDE;
#pragma unroll
    for (int i = 0; i < 4; i++) {
        int d = ty * 4 + i;
        float x0, x1, x2, x3;
        unpack2(acc[i][0], x0, x1);
        unpack2(acc[i][1], x2, x3);
        *(float4*)&np[d * D + (tx << 2)] = make_float4(x0, x1, x2, x3);
    }
    if (tid < D) np[D * D + tid] = zacc;
}

// ================= Kernel 2: reduce splits + normalize -> g_ctx =============
// grid (BH, 4): each CTA handles 1024 of 4096 elements.
__global__ void __launch_bounds__(256) reduce_ctx_kernel() {
    const int head = blockIdx.x;
    const int tid = threadIdx.x;
    __shared__ float zs[D];
    const float* pb = g_part + (size_t)head * SPLITS * PART_STRIDE;

    if (tid < D) {
        float s = 0.0f;
#pragma unroll
        for (int sp = 0; sp < SPLITS; sp++) s += pb[sp * PART_STRIDE + D * D + tid];
        zs[tid] = 1.0f / s;
    }
    __syncthreads();

    const int i0 = blockIdx.y * 1024;
    for (int i = i0 + tid; i < i0 + 1024; i += 256) {
        float s = 0.0f;
#pragma unroll
        for (int sp = 0; sp < SPLITS; sp++) s += pb[sp * PART_STRIDE + i];
        g_ctx[head * D * D + i] = s * zs[i >> 6];
    }
}

// ================= Kernel 3: out = (softmax_ch(q)/8) @ ctx ==================
// grid (BH, 32), 256 threads, 4 row-tiles of 64 per CTA (ctx reuse x4).
// pT2[d][2*(r ^ h(d)) + {0,1}] = exp(q[r,d]) duplicated; h(d)=((d>>2)&15)^((d&3)<<2)
#define QTILES 4
__global__ void __launch_bounds__(256) out_kernel(
    const float* __restrict__ q, float* __restrict__ out) {
    const int head = blockIdx.x;
    const int tile0 = blockIdx.y * QTILES;
    const int tid = threadIdx.x;
    const int tx = tid & 15;   // e-group
    const int ty = tid >> 4;   // row-group

    __shared__ __align__(16) float ctx[D][D + 4];   // 17 KB (pad 68)
    __shared__ __align__(16) float pT2[D][2 * D];   // 32 KB
    __shared__ float ssum[D];

    // stage ctx for this head
    const float* gc = g_ctx + (size_t)head * D * D;
    for (int i = tid; i < (D * D) / 4; i += 256) {
        int d = i >> 4, e4 = (i & 15) << 2;
        *(float4*)&ctx[d][e4] = *(const float4*)&gc[d * D + e4];
    }

    const float* qh = q + (size_t)head * SEQ * D;
    float4 qreg[4];
#pragma unroll
    for (int it = 0; it < 4; it++) {
        int i = tid + it * 256;
        qreg[it] = *(const float4*)&qh[(size_t)tile0 * 64 * D + (i >> 4) * D + ((i & 15) << 2)];
    }
    __syncthreads();

    for (int t = 0; t < QTILES; t++) {
        // ---- stage exp(q) duplicated + row sums via shfl ----
#pragma unroll
        for (int it = 0; it < 4; it++) {
            int i = tid + it * 256;
            int r = i >> 4;        // 0..63
            int cc = i & 15;       // col group; d = 4*cc + j, h(d) = cc ^ (j<<2)
            float e0 = __expf(qreg[it].x), e1 = __expf(qreg[it].y);
            float e2 = __expf(qreg[it].z), e3 = __expf(qreg[it].w);
            float2 pp;
            pp.x = pp.y = e0; *(float2*)&pT2[4 * cc + 0][2 * (r ^ (cc ^ 0))] = pp;
            pp.x = pp.y = e1; *(float2*)&pT2[4 * cc + 1][2 * (r ^ (cc ^ 4))] = pp;
            pp.x = pp.y = e2; *(float2*)&pT2[4 * cc + 2][2 * (r ^ (cc ^ 8))] = pp;
            pp.x = pp.y = e3; *(float2*)&pT2[4 * cc + 3][2 * (r ^ (cc ^ 12))] = pp;
            float part = (e0 + e1) + (e2 + e3);
            part += __shfl_xor_sync(0xffffffffu, part, 8);
            part += __shfl_xor_sync(0xffffffffu, part, 4);
            part += __shfl_xor_sync(0xffffffffu, part, 2);
            part += __shfl_xor_sync(0xffffffffu, part, 1);
            if (cc == 0) ssum[r] = part;
        }
        __syncthreads();

        // prefetch next tile while computing this one
        if (t + 1 < QTILES) {
#pragma unroll
            for (int it = 0; it < 4; it++) {
                int i = tid + it * 256;
                qreg[it] = *(const float4*)&qh[(size_t)(tile0 + t + 1) * 64 * D +
                                               (i >> 4) * D + ((i & 15) << 2)];
            }
        }

        // ---- compute 64x64 tile: out[r,e] = sum_d p[r,d]*ctx[d,e] ----
        ull acc[4][2];
#pragma unroll
        for (int i = 0; i < 4; i++) { acc[i][0] = 0ULL; acc[i][1] = 0ULL; }

#pragma unroll
        for (int d = 0; d < D; d++) {
            const int h = ((d >> 2) & 15) ^ ((d & 3) << 2);
            ulonglong2 B = *(const ulonglong2*)&ctx[d][tx << 2];
#pragma unroll
            for (int i = 0; i < 4; i++) {
                ull a = *(const ull*)&pT2[d][2 * ((ty * 4 + i) ^ h)];
                fma2(acc[i][0], a, B.x);
                fma2(acc[i][1], a, B.y);
            }
        }

        // ---- epilogue ----
        float* ob = out + (size_t)head * SEQ * D + (size_t)(tile0 + t) * 64 * D;
#pragma unroll
        for (int i = 0; i < 4; i++) {
            int r = ty * 4 + i;
            float f = 0.125f / ssum[r];
            float x0, x1, x2, x3;
            unpack2(acc[i][0], x0, x1);
            unpack2(acc[i][1], x2, x3);
            *(float4*)&ob[r * D + (tx << 2)] = make_float4(x0 * f, x1 * f, x2 * f, x3 * f);
        }
        __syncthreads();   // protect pT2/ssum before next tile's staging
    }
}

// ================= launch =================
extern "C" void kernel_launch(void* const* d_in, const int* in_sizes, int n_in,
                              void* d_out, int out_size) {
    const float* q = (const float*)d_in[0];
    const float* k = (const float*)d_in[1];
    const float* v = (const float*)d_in[2];
    float* out = (float*)d_out;
    (void)in_sizes; (void)n_in; (void)out_size;

    ctx_partial_kernel<<<dim3(BH, SPLITS), 256>>>(k, v);
    reduce_ctx_kernel<<<dim3(BH, 4), 256>>>();
    out_kernel<<<dim3(BH, SEQ / 64 / QTILES), 256>>>(q, out);
}

// round 4
// speedup vs baseline: 1.0059x; 1.0059x over previous
#include <cuda_runtime.h>

#define BH 64
#define SEQ 8192
#define D 64
#define SPLITS 8
#define RPS (SEQ / SPLITS)       // 1024 rows per split
#define CHUNK 16
#define NCH (RPS / CHUNK)        // 64 chunks
#define PART_STRIDE (D * D + D)  // numer[4096] + z[64]

__device__ float g_part[BH * SPLITS * PART_STRIDE];  // ~8.5 MB scratch
__device__ float g_ctx[BH * D * D];

typedef unsigned long long ull;

__device__ __forceinline__ void fma2(ull& acc, ull a, ull b) {
    asm("fma.rn.f32x2 %0, %1, %2, %0;" : "+l"(acc) : "l"(a), "l"(b));
}
__device__ __forceinline__ void unpack2(ull v, float& x, float& y) {
    asm("mov.b64 {%0, %1}, %2;" : "=f"(x), "=f"(y) : "l"(v));
}

// ================= Kernel 1: partial context  exp(K)^T @ V  =================
// grid (BH, SPLITS), 256 threads. Double-buffered smem, pre-packed pairs.
// ek2[r][2*pi(d)+{0,1}] = exp(k[r,d]) duplicated; pi(d)=((d&3)<<4)|(d>>2)
// (permutation makes the duplicated STS.64 conflict-free).
__global__ void __launch_bounds__(256) ctx_partial_kernel(
    const float* __restrict__ k, const float* __restrict__ v) {
    const int head = blockIdx.x, split = blockIdx.y;
    const float* kb = k + (size_t)head * SEQ * D + (size_t)split * RPS * D;
    const float* vb = v + (size_t)head * SEQ * D + (size_t)split * RPS * D;

    __shared__ __align__(16) float ek2[2][CHUNK][2 * D];   // 16 KB
    __shared__ __align__(16) float vv[2][CHUNK][D + 4];    // 8.5 KB (pad 68)

    const int tid = threadIdx.x;
    const int tx = tid & 15;        // e-group (compute)
    const int ty = tid >> 4;        // d-group (compute)
    const int kr = tid >> 4;        // staging row 0..15
    const int c16 = tid & 15;       // staging col group
    const int kc4 = c16 << 2;

    ull acc[4][2];
#pragma unroll
    for (int i = 0; i < 4; i++) { acc[i][0] = 0ULL; acc[i][1] = 0ULL; }
    float zacc = 0.0f;

    float4 kreg = *(const float4*)&kb[kr * D + kc4];
    float4 vreg = *(const float4*)&vb[kr * D + kc4];

    // store chunk 0 -> buf 0
    {
        float2 pp;
        pp.x = pp.y = __expf(kreg.x); *(float2*)&ek2[0][kr][2 * (0 * 16 + c16)] = pp;
        pp.x = pp.y = __expf(kreg.y); *(float2*)&ek2[0][kr][2 * (1 * 16 + c16)] = pp;
        pp.x = pp.y = __expf(kreg.z); *(float2*)&ek2[0][kr][2 * (2 * 16 + c16)] = pp;
        pp.x = pp.y = __expf(kreg.w); *(float2*)&ek2[0][kr][2 * (3 * 16 + c16)] = pp;
        *(float4*)&vv[0][kr][kc4] = vreg;
    }
    __syncthreads();

    for (int c = 0; c < NCH; c++) {
        const int p = c & 1;
        if (c + 1 < NCH) {
            kreg = *(const float4*)&kb[(c + 1) * CHUNK * D + kr * D + kc4];
            vreg = *(const float4*)&vb[(c + 1) * CHUNK * D + kr * D + kc4];
        }
#pragma unroll
        for (int r = 0; r < CHUNK; r++) {
            ulonglong2 B = *(const ulonglong2*)&vv[p][r][tx << 2];
#pragma unroll
            for (int i = 0; i < 4; i++) {
                // d = ty*4+i  ->  pi(d) = (i<<4)|ty
                ull a = *(const ull*)&ek2[p][r][2 * ((i << 4) | ty)];
                fma2(acc[i][0], a, B.x);
                fma2(acc[i][1], a, B.y);
            }
        }
        if (tid < D) {
            const int g2 = 2 * (((tid & 3) << 4) | (tid >> 2));
#pragma unroll
            for (int r = 0; r < CHUNK; r++) zacc += ek2[p][r][g2];
        }
        if (c + 1 < NCH) {
            const int b = p ^ 1;
            float2 pp;
            pp.x = pp.y = __expf(kreg.x); *(float2*)&ek2[b][kr][2 * (0 * 16 + c16)] = pp;
            pp.x = pp.y = __expf(kreg.y); *(float2*)&ek2[b][kr][2 * (1 * 16 + c16)] = pp;
            pp.x = pp.y = __expf(kreg.z); *(float2*)&ek2[b][kr][2 * (2 * 16 + c16)] = pp;
            pp.x = pp.y = __expf(kreg.w); *(float2*)&ek2[b][kr][2 * (3 * 16 + c16)] = pp;
            *(float4*)&vv[b][kr][kc4] = vreg;
        }
        __syncthreads();
    }

    float* np = g_part + (size_t)(head * SPLITS + split) * PART_STRIDE;
#pragma unroll
    for (int i = 0; i < 4; i++) {
        int d = ty * 4 + i;
        float x0, x1, x2, x3;
        unpack2(acc[i][0], x0, x1);
        unpack2(acc[i][1], x2, x3);
        *(float4*)&np[d * D + (tx << 2)] = make_float4(x0, x1, x2, x3);
    }
    if (tid < D) np[D * D + tid] = zacc;
}

// ================= Kernel 2: reduce splits + normalize -> g_ctx =============
// grid (BH, 4): each CTA handles 1024 of 4096 elements.
__global__ void __launch_bounds__(256) reduce_ctx_kernel() {
    const int head = blockIdx.x;
    const int tid = threadIdx.x;
    __shared__ float zs[D];
    const float* pb = g_part + (size_t)head * SPLITS * PART_STRIDE;

    if (tid < D) {
        float s = 0.0f;
#pragma unroll
        for (int sp = 0; sp < SPLITS; sp++) s += pb[sp * PART_STRIDE + D * D + tid];
        zs[tid] = 1.0f / s;
    }
    __syncthreads();

    const int i0 = blockIdx.y * 1024;
    for (int i = i0 + tid; i < i0 + 1024; i += 256) {
        float s = 0.0f;
#pragma unroll
        for (int sp = 0; sp < SPLITS; sp++) s += pb[sp * PART_STRIDE + i];
        g_ctx[head * D * D + i] = s * zs[i >> 6];
    }
}

// ================= Kernel 3: out = (softmax_ch(q)/8) @ ctx ==================
// grid (BH, 32), 256 threads, 4 row-tiles of 64 per CTA (ctx reuse x4).
// pT2[d][2*(r ^ h(d)) + {0,1}] = exp(q[r,d]) duplicated; h(d)=((d>>2)&15)^((d&3)<<2)
#define QTILES 4
__global__ void __launch_bounds__(256) out_kernel(
    const float* __restrict__ q, float* __restrict__ out) {
    const int head = blockIdx.x;
    const int tile0 = blockIdx.y * QTILES;
    const int tid = threadIdx.x;
    const int tx = tid & 15;   // e-group
    const int ty = tid >> 4;   // row-group

    __shared__ __align__(16) float ctx[D][D + 4];   // 17 KB (pad 68)
    __shared__ __align__(16) float pT2[D][2 * D];   // 32 KB
    __shared__ float ssum[D];

    // stage ctx for this head
    const float* gc = g_ctx + (size_t)head * D * D;
    for (int i = tid; i < (D * D) / 4; i += 256) {
        int d = i >> 4, e4 = (i & 15) << 2;
        *(float4*)&ctx[d][e4] = *(const float4*)&gc[d * D + e4];
    }

    const float* qh = q + (size_t)head * SEQ * D;
    float4 qreg[4];
#pragma unroll
    for (int it = 0; it < 4; it++) {
        int i = tid + it * 256;
        qreg[it] = *(const float4*)&qh[(size_t)tile0 * 64 * D + (i >> 4) * D + ((i & 15) << 2)];
    }
    __syncthreads();

    for (int t = 0; t < QTILES; t++) {
        // ---- stage exp(q) duplicated + row sums via shfl ----
#pragma unroll
        for (int it = 0; it < 4; it++) {
            int i = tid + it * 256;
            int r = i >> 4;        // 0..63
            int cc = i & 15;       // col group; d = 4*cc + j, h(d) = cc ^ (j<<2)
            float e0 = __expf(qreg[it].x), e1 = __expf(qreg[it].y);
            float e2 = __expf(qreg[it].z), e3 = __expf(qreg[it].w);
            float2 pp;
            pp.x = pp.y = e0; *(float2*)&pT2[4 * cc + 0][2 * (r ^ (cc ^ 0))] = pp;
            pp.x = pp.y = e1; *(float2*)&pT2[4 * cc + 1][2 * (r ^ (cc ^ 4))] = pp;
            pp.x = pp.y = e2; *(float2*)&pT2[4 * cc + 2][2 * (r ^ (cc ^ 8))] = pp;
            pp.x = pp.y = e3; *(float2*)&pT2[4 * cc + 3][2 * (r ^ (cc ^ 12))] = pp;
            float part = (e0 + e1) + (e2 + e3);
            part += __shfl_xor_sync(0xffffffffu, part, 8);
            part += __shfl_xor_sync(0xffffffffu, part, 4);
            part += __shfl_xor_sync(0xffffffffu, part, 2);
            part += __shfl_xor_sync(0xffffffffu, part, 1);
            if (cc == 0) ssum[r] = part;
        }
        __syncthreads();

        // prefetch next tile while computing this one
        if (t + 1 < QTILES) {
#pragma unroll
            for (int it = 0; it < 4; it++) {
                int i = tid + it * 256;
                qreg[it] = *(const float4*)&qh[(size_t)(tile0 + t + 1) * 64 * D +
                                               (i >> 4) * D + ((i & 15) << 2)];
            }
        }

        // ---- compute 64x64 tile: out[r,e] = sum_d p[r,d]*ctx[d,e] ----
        ull acc[4][2];
#pragma unroll
        for (int i = 0; i < 4; i++) { acc[i][0] = 0ULL; acc[i][1] = 0ULL; }

#pragma unroll
        for (int d = 0; d < D; d++) {
            const int h = ((d >> 2) & 15) ^ ((d & 3) << 2);
            ulonglong2 B = *(const ulonglong2*)&ctx[d][tx << 2];
#pragma unroll
            for (int i = 0; i < 4; i++) {
                ull a = *(const ull*)&pT2[d][2 * ((ty * 4 + i) ^ h)];
                fma2(acc[i][0], a, B.x);
                fma2(acc[i][1], a, B.y);
            }
        }

        // ---- epilogue ----
        float* ob = out + (size_t)head * SEQ * D + (size_t)(tile0 + t) * 64 * D;
#pragma unroll
        for (int i = 0; i < 4; i++) {
            int r = ty * 4 + i;
            float f = 0.125f / ssum[r];
            float x0, x1, x2, x3;
            unpack2(acc[i][0], x0, x1);
            unpack2(acc[i][1], x2, x3);
            *(float4*)&ob[r * D + (tx << 2)] = make_float4(x0 * f, x1 * f, x2 * f, x3 * f);
        }
        __syncthreads();   // protect pT2/ssum before next tile's staging
    }
}

// ================= launch =================
extern "C" void kernel_launch(void* const* d_in, const int* in_sizes, int n_in,
                              void* d_out, int out_size) {
    const float* q = (const float*)d_in[0];
    const float* k = (const float*)d_in[1];
    const float* v = (const float*)d_in[2];
    float* out = (float*)d_out;
    (void)in_sizes; (void)n_in; (void)out_size;

    ctx_partial_kernel<<<dim3(BH, SPLITS), 256>>>(k, v);
    reduce_ctx_kernel<<<dim3(BH, 4), 256>>>();
    out_kernel<<<dim3(BH, SEQ / 64 / QTILES), 256>>>(q, out);
}